// round 12
// baseline (speedup 1.0000x reference)
#include <cuda_runtime.h>
#include <cuda_bf16.h>
#include <cstdint>

#define EMBED 100
#define BATCH 8192
#define VEC4_PER_MAT 2500   // 100*100/4
#define F4_PER_ROW   25     // 100/4
#define NTHREADS     256
#define ITERS        10     // ceil(2500/256); iters 0..8 always in-bounds

#define SORT_THREADS 1024
#define ELEMS_PER_THR (BATCH / SORT_THREADS)  // 8
#define BUCKET_DIV   40
#define NBUCKETS     250    // ceil(10000/40)

// perm word: (functor_id << 13) | batch_index   (b < 8192 fits in 13 bits)
__device__ int g_perm[BATCH];

// ---------------------------------------------------------------------------
// Coarse bucket sort: group batch elements by functor/40. All duplicates of a
// functor land in one ~33-element bucket -> adjacent CTAs -> L2 hits.
// Single CTA, smem-only histogram over 250 bins. Deterministic output overall
// (scatter order within a bucket is irrelevant: main kernel writes out[b]).
// ---------------------------------------------------------------------------
__global__ __launch_bounds__(SORT_THREADS)
void bucket_sort_kernel(const int* __restrict__ Xf)
{
    __shared__ int hist[NBUCKETS];
    __shared__ int offs[NBUCKETS];
    __shared__ int wsum[SORT_THREADS / 32];

    const int t = threadIdx.x;
    const int lane = t & 31, w = t >> 5;

    if (t < NBUCKETS) hist[t] = 0;
    __syncthreads();

    int f[ELEMS_PER_THR], bk[ELEMS_PER_THR];
    #pragma unroll
    for (int i = 0; i < ELEMS_PER_THR; i++) {
        f[i]  = Xf[t + i * SORT_THREADS];
        bk[i] = f[i] / BUCKET_DIV;
        atomicAdd(&hist[bk[i]], 1);
    }
    __syncthreads();

    // Block-wide exclusive scan over the 250 bins (all threads participate;
    // threads >= NBUCKETS contribute 0 so no divergence around barriers).
    int v = (t < NBUCKETS) ? hist[t] : 0;
    int x = v;
    #pragma unroll
    for (int o = 1; o < 32; o <<= 1) {
        int y = __shfl_up_sync(0xFFFFFFFFu, x, o);
        if (lane >= o) x += y;
    }
    if (lane == 31) wsum[w] = x;
    __syncthreads();
    if (w == 0) {
        int s = wsum[lane];
        #pragma unroll
        for (int o = 1; o < 32; o <<= 1) {
            int y = __shfl_up_sync(0xFFFFFFFFu, s, o);
            if (lane >= o) s += y;
        }
        wsum[lane] = s;
    }
    __syncthreads();
    const int excl = (x - v) + (w > 0 ? wsum[w - 1] : 0);
    if (t < NBUCKETS) offs[t] = excl;
    __syncthreads();

    // Scatter packed (f, b) words grouped by bucket.
    #pragma unroll
    for (int i = 0; i < ELEMS_PER_THR; i++) {
        const int b   = t + i * SORT_THREADS;
        const int pos = atomicAdd(&offs[bk[i]], 1);
        g_perm[pos] = (f[i] << 13) | b;
    }
}

// ---------------------------------------------------------------------------
// out[b] = ctx[b]^T * M[f] * arg[b]   (R6 LDG mainloop, b/f from packed perm)
// ---------------------------------------------------------------------------
__global__ __launch_bounds__(NTHREADS)
void matrix_skipgram_kernel(const int* __restrict__ X_argument,
                            const int* __restrict__ X_context,
                            const float* __restrict__ noun_matrix,
                            const float* __restrict__ functor_table,
                            const float* __restrict__ context_table,
                            float* __restrict__ out)
{
    const int pb = g_perm[blockIdx.x];
    const int b  = pb & 8191;
    const int f  = pb >> 13;
    const int t  = threadIdx.x;

    __shared__ float s_arg[EMBED];
    __shared__ float s_ctx[EMBED];
    __shared__ float s_red[NTHREADS / 32];

    {
        const float* av = noun_matrix   + (size_t)X_argument[b] * EMBED;
        const float* cv = context_table + (size_t)X_context[b]  * EMBED;
        if (t < EMBED) {
            s_arg[t] = av[t];
            s_ctx[t] = cv[t];
        }
    }

    const float4* __restrict__ M =
        reinterpret_cast<const float4*>(functor_table + (size_t)f * (EMBED * EMBED));

    // Unconditional front-batched loads: 10 independent LDG.128 per thread.
    const int k9  = t + 9 * NTHREADS;
    const bool v9 = (k9 < VEC4_PER_MAT);
    float4 m[ITERS];
    #pragma unroll
    for (int it = 0; it < ITERS - 1; ++it)
        m[it] = __ldg(&M[t + it * NTHREADS]);
    m[ITERS - 1] = __ldg(&M[v9 ? k9 : 0]);

    __syncthreads();   // s_arg/s_ctx ready; matrix loads already in flight

    float acc = 0.0f;
    #pragma unroll
    for (int it = 0; it < ITERS - 1; ++it) {
        const int k  = t + it * NTHREADS;
        const int i  = k / F4_PER_ROW;
        const int j4 = (k - i * F4_PER_ROW) * 4;
        float dot = m[it].x * s_arg[j4]
                  + m[it].y * s_arg[j4 + 1]
                  + m[it].z * s_arg[j4 + 2]
                  + m[it].w * s_arg[j4 + 3];
        acc = fmaf(s_ctx[i], dot, acc);
    }
    {   // masked last iteration
        const int k  = v9 ? k9 : 0;
        const int i  = k / F4_PER_ROW;
        const int j4 = (k - i * F4_PER_ROW) * 4;
        float dot = m[ITERS - 1].x * s_arg[j4]
                  + m[ITERS - 1].y * s_arg[j4 + 1]
                  + m[ITERS - 1].z * s_arg[j4 + 2]
                  + m[ITERS - 1].w * s_arg[j4 + 3];
        const float c = v9 ? s_ctx[i] : 0.0f;
        acc = fmaf(c, dot, acc);
    }

    #pragma unroll
    for (int o = 16; o > 0; o >>= 1)
        acc += __shfl_xor_sync(0xFFFFFFFFu, acc, o);

    if ((t & 31) == 0)
        s_red[t >> 5] = acc;
    __syncthreads();

    if (t < (NTHREADS / 32)) {
        acc = s_red[t];
        #pragma unroll
        for (int o = (NTHREADS / 64); o > 0; o >>= 1)
            acc += __shfl_xor_sync(0xFFu, acc, o);
        if (t == 0)
            out[b] = acc;
    }
}

extern "C" void kernel_launch(void* const* d_in, const int* in_sizes, int n_in,
                              void* d_out, int out_size)
{
    const int*   X_argument    = (const int*)  d_in[0];
    const int*   X_functor     = (const int*)  d_in[1];
    const int*   X_context     = (const int*)  d_in[2];
    const float* noun_matrix   = (const float*)d_in[3];
    const float* functor_table = (const float*)d_in[4];
    const float* context_table = (const float*)d_in[5];
    float* out = (float*)d_out;

    bucket_sort_kernel<<<1, SORT_THREADS>>>(X_functor);
    matrix_skipgram_kernel<<<BATCH, NTHREADS>>>(
        X_argument, X_context,
        noun_matrix, functor_table, context_table, out);
}